// round 14
// baseline (speedup 1.0000x reference)
#include <cuda_runtime.h>
#include <stdint.h>

typedef unsigned long long ull;

#define DD     1024
#define LLEN   2048
#define KK     32
#define KQ     8            // poles per lane (4-way k-split)
#define NSLOT  4            // 8 poles per lane, packed in pairs
#define SEG    512          // time-segment per warp
#define SREC   8            // recurrence stride
#define STEPS  (SEG / SREC)     // 64 steps

// ---- packed f32x2 helpers (sm_100+ PTX; ptxas never emits these from C++) ----
__device__ __forceinline__ ull f2pack(float lo, float hi) {
    ull r;
    asm("mov.b64 %0, {%1, %2};" : "=l"(r) : "r"(__float_as_uint(lo)), "r"(__float_as_uint(hi)));
    return r;
}
__device__ __forceinline__ void f2unpack(ull v, float& lo, float& hi) {
    unsigned a, b;
    asm("mov.b64 {%0, %1}, %2;" : "=r"(a), "=r"(b) : "l"(v));
    lo = __uint_as_float(a);
    hi = __uint_as_float(b);
}
__device__ __forceinline__ ull f2add(ull a, ull b) {
    ull d; asm("add.rn.f32x2 %0, %1, %2;" : "=l"(d) : "l"(a), "l"(b)); return d;
}
__device__ __forceinline__ ull f2mul(ull a, ull b) {
    ull d; asm("mul.rn.f32x2 %0, %1, %2;" : "=l"(d) : "l"(a), "l"(b)); return d;
}
__device__ __forceinline__ ull f2fma(ull a, ull b, ull c) {
    ull d; asm("fma.rn.f32x2 %0, %1, %2, %3;" : "=l"(d) : "l"(a), "l"(b), "l"(c)); return d;
}

__device__ __forceinline__ float reduce4(const ull* x) {
    ull c0 = f2add(x[0], x[1]);
    ull c1 = f2add(x[2], x[3]);
    ull t  = f2add(c0, c1);
    float lo, hi;
    f2unpack(t, lo, hi);
    return lo + hi;
}

// x_k[t] = Re(R_k p_k^t) obeys the stride-8 real recurrence
//   x[t] = A_k x[t-8] + B_k x[t-16],  A_k = 2 Re(p^8),  B_k = -|p^8|^2.
// CTA = 128 threads = one row d; warp seg covers t in [seg*512, (seg+1)*512).
// Lane = (kq = lane>>3 pole-quarter of 8 poles, tsub = lane&7 time offset).
// Merge per step: shfl.xor(8)+add, shfl.xor(16)+add; kq==0 lanes store.
// Stage 1 builds rot[k][j] = p^j (j<16) and base[k][seg] = R*p^(512*seg-9) in
// smem. Stage 2 seeds registers in TWO narrow loops (A/B first, then x1/x2) so
// the live window never exceeds the register cap (R11-R13 spilled here).
// launch_bounds(128,7): 73-reg cap, 7 CTAs/SM = 1036 >= 1024 -> single wave.
__global__ void __launch_bounds__(128, 7) modal_kernel(
    const float* __restrict__ rr, const float* __restrict__ th,
    const float* __restrict__ Rre, const float* __restrict__ Rim,
    const float* __restrict__ h0, float* __restrict__ out)
{
    __shared__ float2 sh_rot[KK][16];   // p_k^j, j = 0..15
    __shared__ float2 sh_base[KK][4];   // R_k * p_k^(512*seg - 9)

    const int tid  = threadIdx.x;
    const int lane = tid & 31;
    const int seg  = tid >> 5;          // 4 warps = 4 time segments
    const int d    = blockIdx.x;
    const int tsub = lane & 7;
    const int kq   = lane >> 3;

    const float INV2PI = 0.15915494309189535f;
    const float PI2_HI = 6.2831854820251465f;   // fp32(2*pi)
    const float PI2_LO = -1.7484555e-7f;        // 2*pi - PI2_HI

    // ---- stage 1: tables. thread -> (k = tid&31, part = tid>>5) ----
    {
        const int k    = tid & 31;
        const int part = tid >> 5;
        const int off  = k * DD + d;
        float rk = __ldg(rr + off);
        float tk = __ldg(th + off);
        float lr = __logf(rk);

        // rot[k][part*4 .. part*4+3] = p^j  (j <= 15, angle <= ~95 rad)
#pragma unroll
        for (int jj = 0; jj < 4; ++jj) {
            int j = part * 4 + jj;
            float jf = (float)j;
            float rad = __expf(jf * lr);
            float a = jf * tk;
            float n = rintf(a * INV2PI);
            a = fmaf(-n, PI2_HI, a);
            a = fmaf(-n, PI2_LO, a);
            float s, c;
            __sincosf(a, &s, &c);
            sh_rot[k][j] = make_float2(rad * c, rad * s);
        }

        // base[k][part] = R * p^(512*part - 9): exact twoProd + 2-term Cody-Waite
        {
            float ar = __ldg(Rre + off);
            float ai = __ldg(Rim + off);
            float ef = 512.0f * (float)part - 9.0f;     // exact in fp32
            float rad = __expf(ef * lr);
            float ph = ef * tk;
            float pe = fmaf(ef, tk, -ph);               // exact low part
            float n = rintf(ph * INV2PI);
            float a = fmaf(-n, PI2_HI, ph);
            a = a + pe;
            a = fmaf(-n, PI2_LO, a);
            float s, c;
            __sincosf(a, &s, &c);
            sh_base[k][part] = make_float2(rad * (ar * c - ai * s),
                                           rad * (ar * s + ai * c));
        }
    }
    __syncthreads();

    // ---- stage 2a: coefficients A, B (narrow live window: only rot[k][8]) ----
    ull x1[NSLOT], x2[NSLOT], A[NSLOT], B[NSLOT];
    {
        float p_A = 0.f, p_B = 0.f;
#pragma unroll
        for (int kk = 0; kk < KQ; ++kk) {
            const int k = kq * KQ + kk;
            float2 r8 = sh_rot[k][8];
            float cA = 2.0f * r8.x;
            float cB = -(r8.x * r8.x + r8.y * r8.y);
            if (kk & 1) {
                A[kk >> 1] = f2pack(p_A, cA);
                B[kk >> 1] = f2pack(p_B, cB);
            } else {
                p_A = cA; p_B = cB;
            }
        }
    }

    // ---- stage 2b: seeds x1, x2 (narrow live window: rj, rj8, base) ----
    {
        float p_x1 = 0.f, p_x2 = 0.f;
#pragma unroll
        for (int kk = 0; kk < KQ; ++kk) {
            const int k = kq * KQ + kk;
            float2 rj  = sh_rot[k][tsub];       // p^tsub
            float2 rj8 = sh_rot[k][tsub + 8];   // p^(tsub+8)
            float2 b   = sh_base[k][seg];       // R*p^(512*seg - 9)
            // x2 at exponent 512*seg + tsub - 9, x1 at +8
            float cx2 = b.x * rj.x  - b.y * rj.y;
            float cx1 = b.x * rj8.x - b.y * rj8.y;
            if (kk & 1) {
                x1[kk >> 1] = f2pack(p_x1, cx1);
                x2[kk >> 1] = f2pack(p_x2, cx2);
            } else {
                p_x1 = cx1; p_x2 = cx2;
            }
        }
    }

    float* outp = out + (size_t)d * LLEN + seg * SEG + tsub;
    const bool do_store = (kq == 0);

    // 2-step unrolled main loop; x1/x2 swap roles each step (no register moves)
#pragma unroll 1
    for (int i = 0; i < STEPS; i += 2) {
        {
            float part = reduce4(x1);
            float s = part + __shfl_xor_sync(0xffffffffu, part, 8);
            s = s + __shfl_xor_sync(0xffffffffu, s, 16);
            if (do_store) outp[i * SREC] = s;
        }
#pragma unroll
        for (int s2 = 0; s2 < NSLOT; ++s2)
            x2[s2] = f2fma(A[s2], x1[s2], f2mul(B[s2], x2[s2]));
        {
            float part = reduce4(x2);
            float s = part + __shfl_xor_sync(0xffffffffu, part, 8);
            s = s + __shfl_xor_sync(0xffffffffu, s, 16);
            if (do_store) outp[(i + 1) * SREC] = s;
        }
#pragma unroll
        for (int s2 = 0; s2 < NSLOT; ++s2)
            x1[s2] = f2fma(A[s2], x2[s2], f2mul(B[s2], x1[s2]));
    }

    // l == 0 carries h_0; same thread (seg 0, lane 0) wrote l=0 above
    if (seg == 0 && lane == 0) {
        out[(size_t)d * LLEN] = __ldg(h0 + d);
    }
}

extern "C" void kernel_launch(void* const* d_in, const int* in_sizes, int n_in,
                              void* d_out, int out_size) {
    const float* rr  = (const float*)d_in[0];
    const float* th  = (const float*)d_in[1];
    const float* Rre = (const float*)d_in[2];
    const float* Rim = (const float*)d_in[3];
    const float* h0  = (const float*)d_in[4];
    float* out = (float*)d_out;
    modal_kernel<<<DD, 128>>>(rr, th, Rre, Rim, h0, out);
}

// round 15
// speedup vs baseline: 1.1155x; 1.1155x over previous
#include <cuda_runtime.h>
#include <stdint.h>

typedef unsigned long long ull;

#define DD     1024
#define LLEN   2048
#define KK     32
#define KQ     8            // poles per lane (4-way k-split)
#define NSLOT  4            // 8 poles per lane, packed in pairs
#define SEG    512          // time-segment per warp
#define SREC   8            // recurrence stride
#define STEPS  (SEG / SREC)     // 64 steps

// ---- packed f32x2 helpers (sm_100+ PTX; ptxas never emits these from C++) ----
__device__ __forceinline__ ull f2pack(float lo, float hi) {
    ull r;
    asm("mov.b64 %0, {%1, %2};" : "=l"(r) : "r"(__float_as_uint(lo)), "r"(__float_as_uint(hi)));
    return r;
}
__device__ __forceinline__ void f2unpack(ull v, float& lo, float& hi) {
    unsigned a, b;
    asm("mov.b64 {%0, %1}, %2;" : "=r"(a), "=r"(b) : "l"(v));
    lo = __uint_as_float(a);
    hi = __uint_as_float(b);
}
__device__ __forceinline__ ull f2add(ull a, ull b) {
    ull d; asm("add.rn.f32x2 %0, %1, %2;" : "=l"(d) : "l"(a), "l"(b)); return d;
}
__device__ __forceinline__ ull f2mul(ull a, ull b) {
    ull d; asm("mul.rn.f32x2 %0, %1, %2;" : "=l"(d) : "l"(a), "l"(b)); return d;
}
__device__ __forceinline__ ull f2fma(ull a, ull b, ull c) {
    ull d; asm("fma.rn.f32x2 %0, %1, %2, %3;" : "=l"(d) : "l"(a), "l"(b), "l"(c)); return d;
}

__device__ __forceinline__ float reduce4(const ull* x) {
    ull c0 = f2add(x[0], x[1]);
    ull c1 = f2add(x[2], x[3]);
    ull t  = f2add(c0, c1);
    float lo, hi;
    f2unpack(t, lo, hi);
    return lo + hi;
}

// x_k[t] = Re(R_k p_k^t) obeys the stride-8 real recurrence
//   x[t] = A_k x[t-8] + B_k x[t-16],  A_k = 2 r^8 cos(8 th),  B_k = -r^16.
// CTA = 128 threads = one row d; warp = one 512-long time segment.
// Lane = (kq = lane>>3 pole-quarter of 8 poles, tsub = lane&7 time offset).
// Merge: shfl.xor(8)+add, shfl.xor(16)+add; kq==0 lanes store.
// Stage 1 (threads 0..31) computes per-k transcendentals once per CTA into
// scalar smem arrays (the R10 structure — float2 table variants trigger a
// ptxas pathology that injects per-iteration L1 traffic; do not reintroduce).
// Main loop is software-pipelined: both advances issue before the two
// shfl-latency-bound merge/store chains, which then overlap each other.
__global__ void __launch_bounds__(128, 8) modal_kernel(
    const float* __restrict__ rr, const float* __restrict__ th,
    const float* __restrict__ Rre, const float* __restrict__ Rim,
    const float* __restrict__ h0, float* __restrict__ out)
{
    __shared__ float sh_lr[KK], sh_r8[KK], sh_s8[KK], sh_c8[KK], sh_th[KK], sh_B[KK];

    const int tid  = threadIdx.x;
    const int lane = tid & 31;
    const int seg  = tid >> 5;              // 4 warps = 4 time segments
    const int d    = blockIdx.x;
    const int tsub = lane & 7;
    const int kq   = lane >> 3;

    const float INV2PI = 0.15915494309189535f;
    const float PI2_HI = 6.2831854820251465f;   // fp32(2*pi)
    const float PI2_LO = -1.7484555e-7f;        // 2*pi - PI2_HI

    // ---- stage 1: per-k shared setup (threads 0..31, one k each) ----
    if (tid < KK) {
        const int off = tid * DD + d;
        float rk = __ldg(rr + off);
        float tk = __ldg(th + off);
        float lr = __logf(rk);
        float r2 = rk * rk, r4 = r2 * r2, r8 = r4 * r4;
        float qa = 8.0f * tk;               // exact (power-of-two scale)
        float nq = rintf(qa * INV2PI);
        qa = fmaf(-nq, PI2_HI, qa);
        qa = fmaf(-nq, PI2_LO, qa);
        float s8, c8;
        __sincosf(qa, &s8, &c8);
        sh_lr[tid] = lr;
        sh_r8[tid] = r8;
        sh_s8[tid] = s8;
        sh_c8[tid] = c8;
        sh_th[tid] = tk;
        sh_B[tid]  = -r8 * r8;
    }
    __syncthreads();

    // ---- stage 2: per-thread seeds; A and B packed in registers ----
    ull x1[NSLOT], x2[NSLOT], A[NSLOT], B[NSLOT];

    // seed exponents: e1 = seg*512 + tsub - 1 (first output), e2 = e1 - 8
    const float t2f = (float)(seg * SEG + tsub - 9);

    float p_x1 = 0.f, p_x2 = 0.f, p_A = 0.f, p_B = 0.f;

#pragma unroll
    for (int kk = 0; kk < KQ; ++kk) {
        const int k = kq * KQ + kk;
        float lr = sh_lr[k];
        float r8 = sh_r8[k];
        float s8 = sh_s8[k];
        float c8 = sh_c8[k];
        float tk = sh_th[k];
        float cB = sh_B[k];
        const int off = k * DD + d;
        float ar = __ldg(Rre + off);
        float ai = __ldg(Rim + off);

        float cA = 2.0f * r8 * c8;

        // seed x2 = x(e2): phase e2*th via exact twoProd + 2-term Cody-Waite
        float radm = __expf(t2f * lr);
        float ph = t2f * tk;
        float pe = fmaf(t2f, tk, -ph);      // exact low part of the product
        float n2 = rintf(ph * INV2PI);
        float a2 = fmaf(-n2, PI2_HI, ph);
        a2 = a2 + pe;
        a2 = fmaf(-n2, PI2_LO, a2);
        float sm, cm;
        __sincosf(a2, &sm, &cm);
        float cx2 = radm * (ar * cm - ai * sm);

        // seed x1 = x(e2+8): rotate phase by 8 th, scale radius by r^8
        float rad0 = radm * r8;
        float c0 = cm * c8 - sm * s8;
        float s0 = sm * c8 + cm * s8;
        float cx1 = rad0 * (ar * c0 - ai * s0);

        if (kk & 1) {
            x1[kk >> 1] = f2pack(p_x1, cx1);
            x2[kk >> 1] = f2pack(p_x2, cx2);
            A [kk >> 1] = f2pack(p_A,  cA);
            B [kk >> 1] = f2pack(p_B,  cB);
        } else {
            p_x1 = cx1; p_x2 = cx2; p_A = cA; p_B = cB;
        }
    }

    float* outp = out + (size_t)d * LLEN + seg * SEG + tsub;
    const bool do_store = (kq == 0);

    // 2-step software-pipelined main loop: both advances issue before the two
    // shfl-bound merge chains; x1/x2 swap roles each step (no register moves).
#pragma unroll 1
    for (int i = 0; i < STEPS; i += 2) {
        float pa = reduce4(x1);                 // partial for step i
#pragma unroll
        for (int s2 = 0; s2 < NSLOT; ++s2)      // advance: x2 <- A*x1 + B*x2
            x2[s2] = f2fma(A[s2], x1[s2], f2mul(B[s2], x2[s2]));
        float pb = reduce4(x2);                 // partial for step i+1
#pragma unroll
        for (int s2 = 0; s2 < NSLOT; ++s2)      // advance: x1 <- A*x2 + B*x1
            x1[s2] = f2fma(A[s2], x2[s2], f2mul(B[s2], x1[s2]));

        // merge + store both steps; the two shfl chains overlap
        float sa = pa + __shfl_xor_sync(0xffffffffu, pa, 8);
        float sb = pb + __shfl_xor_sync(0xffffffffu, pb, 8);
        sa = sa + __shfl_xor_sync(0xffffffffu, sa, 16);
        sb = sb + __shfl_xor_sync(0xffffffffu, sb, 16);
        if (do_store) {
            outp[i * SREC]       = sa;
            outp[(i + 1) * SREC] = sb;
        }
    }

    // l == 0 carries h_0; same thread (seg 0, lane 0) wrote l=0 above
    if (seg == 0 && lane == 0) {
        out[(size_t)d * LLEN] = __ldg(h0 + d);
    }
}

extern "C" void kernel_launch(void* const* d_in, const int* in_sizes, int n_in,
                              void* d_out, int out_size) {
    const float* rr  = (const float*)d_in[0];
    const float* th  = (const float*)d_in[1];
    const float* Rre = (const float*)d_in[2];
    const float* Rim = (const float*)d_in[3];
    const float* h0  = (const float*)d_in[4];
    float* out = (float*)d_out;
    modal_kernel<<<DD, 128>>>(rr, th, Rre, Rim, h0, out);
}

// round 16
// speedup vs baseline: 1.1175x; 1.0019x over previous
#include <cuda_runtime.h>
#include <stdint.h>

typedef unsigned long long ull;

#define DD     1024
#define LLEN   2048
#define KK     32
#define KQ     8            // poles per lane (4-way k-split)
#define NSLOT  4            // 8 poles per lane, packed in pairs
#define SEG    1024         // time-segment per warp (two warps per row d)
#define SREC   8            // recurrence stride
#define STEPS  (SEG / SREC)     // 128 steps per warp

// ---- packed f32x2 helpers (sm_100+ PTX; ptxas never emits these from C++) ----
__device__ __forceinline__ ull f2pack(float lo, float hi) {
    ull r;
    asm("mov.b64 %0, {%1, %2};" : "=l"(r) : "r"(__float_as_uint(lo)), "r"(__float_as_uint(hi)));
    return r;
}
__device__ __forceinline__ void f2unpack(ull v, float& lo, float& hi) {
    unsigned a, b;
    asm("mov.b64 {%0, %1}, %2;" : "=r"(a), "=r"(b) : "l"(v));
    lo = __uint_as_float(a);
    hi = __uint_as_float(b);
}
__device__ __forceinline__ ull f2add(ull a, ull b) {
    ull d; asm("add.rn.f32x2 %0, %1, %2;" : "=l"(d) : "l"(a), "l"(b)); return d;
}
__device__ __forceinline__ ull f2mul(ull a, ull b) {
    ull d; asm("mul.rn.f32x2 %0, %1, %2;" : "=l"(d) : "l"(a), "l"(b)); return d;
}
__device__ __forceinline__ ull f2fma(ull a, ull b, ull c) {
    ull d; asm("fma.rn.f32x2 %0, %1, %2, %3;" : "=l"(d) : "l"(a), "l"(b), "l"(c)); return d;
}

__device__ __forceinline__ float reduce4(const ull* x) {
    ull c0 = f2add(x[0], x[1]);
    ull c1 = f2add(x[2], x[3]);
    ull t  = f2add(c0, c1);
    float lo, hi;
    f2unpack(t, lo, hi);
    return lo + hi;
}

// x_k[t] = Re(R_k p_k^t) obeys the stride-8 real recurrence
//   x[t] = A_k x[t-8] + B_k x[t-16],  A_k = 2 r^8 cos(8 th),  B_k = -r^16.
// CTA = 128 threads = TWO rows d (warps 0,1 -> d0 halves; warps 2,3 -> d1).
// Each warp covers a 1024-long time segment of its row -> 2048 warps total:
// main-loop chip work unchanged vs R10, per-warp setup amortized over 2x the
// outputs (chip setup halves).
// Lane = (kq = lane>>3 pole-quarter of 8 poles, tsub = lane&7 time offset).
// Merge per step: shfl.xor(8)+add, shfl.xor(16)+add; kq==0 lanes store.
// Stage 1 (threads 0..63) computes per-(d,k) transcendentals once per CTA into
// SCALAR smem arrays. (float2/LDS.64 smem tables trigger a ptxas pathology
// that injects per-iteration L1 traffic into the main loop — scalars only.)
__global__ void __launch_bounds__(128, 8) modal_kernel(
    const float* __restrict__ rr, const float* __restrict__ th,
    const float* __restrict__ Rre, const float* __restrict__ Rim,
    const float* __restrict__ h0, float* __restrict__ out)
{
    __shared__ float sh_lr[2][KK], sh_r8[2][KK], sh_s8[2][KK],
                     sh_c8[2][KK], sh_th[2][KK], sh_B[2][KK];

    const int tid  = threadIdx.x;
    const int lane = tid & 31;
    const int w    = tid >> 5;
    const int dl   = w >> 1;                // 0 or 1: which row this warp serves
    const int half = w & 1;                 // which 1024-t half
    const int d    = blockIdx.x * 2 + dl;
    const int tsub = lane & 7;
    const int kq   = lane >> 3;

    const float INV2PI = 0.15915494309189535f;
    const float PI2_HI = 6.2831854820251465f;   // fp32(2*pi)
    const float PI2_LO = -1.7484555e-7f;        // 2*pi - PI2_HI

    // ---- stage 1: per-(d,k) shared setup (threads 0..63: dl' = tid>>5, k = tid&31) ----
    if (tid < 2 * KK) {
        const int dls = tid >> 5;
        const int k   = tid & 31;
        const int off = k * DD + blockIdx.x * 2 + dls;
        float rk = __ldg(rr + off);
        float tk = __ldg(th + off);
        float lr = __logf(rk);
        float r2 = rk * rk, r4 = r2 * r2, r8 = r4 * r4;
        float qa = 8.0f * tk;               // exact (power-of-two scale)
        float nq = rintf(qa * INV2PI);
        qa = fmaf(-nq, PI2_HI, qa);
        qa = fmaf(-nq, PI2_LO, qa);
        float s8, c8;
        __sincosf(qa, &s8, &c8);
        sh_lr[dls][k] = lr;
        sh_r8[dls][k] = r8;
        sh_s8[dls][k] = s8;
        sh_c8[dls][k] = c8;
        sh_th[dls][k] = tk;
        sh_B[dls][k]  = -r8 * r8;
    }
    __syncthreads();

    // ---- stage 2: per-thread seeds; A and B packed in registers ----
    ull x1[NSLOT], x2[NSLOT], A[NSLOT], B[NSLOT];

    // seed exponents: e1 = half*1024 + tsub - 1 (first output), e2 = e1 - 8
    const float t2f = (float)(half * SEG + tsub - 9);

    float p_x1 = 0.f, p_x2 = 0.f, p_A = 0.f, p_B = 0.f;

#pragma unroll
    for (int kk = 0; kk < KQ; ++kk) {
        const int k = kq * KQ + kk;
        float lr = sh_lr[dl][k];
        float r8 = sh_r8[dl][k];
        float s8 = sh_s8[dl][k];
        float c8 = sh_c8[dl][k];
        float tk = sh_th[dl][k];
        float cB = sh_B[dl][k];
        const int off = k * DD + d;
        float ar = __ldg(Rre + off);
        float ai = __ldg(Rim + off);

        float cA = 2.0f * r8 * c8;

        // seed x2 = x(e2): phase e2*th via exact twoProd + 2-term Cody-Waite
        float radm = __expf(t2f * lr);
        float ph = t2f * tk;
        float pe = fmaf(t2f, tk, -ph);      // exact low part of the product
        float n2 = rintf(ph * INV2PI);
        float a2 = fmaf(-n2, PI2_HI, ph);
        a2 = a2 + pe;
        a2 = fmaf(-n2, PI2_LO, a2);
        float sm, cm;
        __sincosf(a2, &sm, &cm);
        float cx2 = radm * (ar * cm - ai * sm);

        // seed x1 = x(e2+8): rotate phase by 8 th, scale radius by r^8
        float rad0 = radm * r8;
        float c0 = cm * c8 - sm * s8;
        float s0 = sm * c8 + cm * s8;
        float cx1 = rad0 * (ar * c0 - ai * s0);

        if (kk & 1) {
            x1[kk >> 1] = f2pack(p_x1, cx1);
            x2[kk >> 1] = f2pack(p_x2, cx2);
            A [kk >> 1] = f2pack(p_A,  cA);
            B [kk >> 1] = f2pack(p_B,  cB);
        } else {
            p_x1 = cx1; p_x2 = cx2; p_A = cA; p_B = cB;
        }
    }

    float* outp = out + (size_t)d * LLEN + half * SEG + tsub;
    const bool do_store = (kq == 0);

    // 2-step unrolled main loop; x1/x2 swap roles each step (no register moves)
#pragma unroll 1
    for (int i = 0; i < STEPS; i += 2) {
        {
            float part = reduce4(x1);
            float s = part + __shfl_xor_sync(0xffffffffu, part, 8);
            s = s + __shfl_xor_sync(0xffffffffu, s, 16);
            if (do_store) outp[i * SREC] = s;
        }
#pragma unroll
        for (int s2 = 0; s2 < NSLOT; ++s2)
            x2[s2] = f2fma(A[s2], x1[s2], f2mul(B[s2], x2[s2]));
        {
            float part = reduce4(x2);
            float s = part + __shfl_xor_sync(0xffffffffu, part, 8);
            s = s + __shfl_xor_sync(0xffffffffu, s, 16);
            if (do_store) outp[(i + 1) * SREC] = s;
        }
#pragma unroll
        for (int s2 = 0; s2 < NSLOT; ++s2)
            x1[s2] = f2fma(A[s2], x2[s2], f2mul(B[s2], x1[s2]));
    }

    // l == 0 carries h_0; the same thread (half 0, lane 0 of each row's warp
    // pair) wrote the l=0 slot in iteration 0, so program order protects this.
    if (half == 0 && lane == 0) {
        out[(size_t)d * LLEN] = __ldg(h0 + d);
    }
}

extern "C" void kernel_launch(void* const* d_in, const int* in_sizes, int n_in,
                              void* d_out, int out_size) {
    const float* rr  = (const float*)d_in[0];
    const float* th  = (const float*)d_in[1];
    const float* Rre = (const float*)d_in[2];
    const float* Rim = (const float*)d_in[3];
    const float* h0  = (const float*)d_in[4];
    float* out = (float*)d_out;
    // 2048 warps: 2 rows per 128-thread CTA, 2 time-halves per row
    modal_kernel<<<DD / 2, 128>>>(rr, th, Rre, Rim, h0, out);
}